// round 17
// baseline (speedup 1.0000x reference)
#include <cuda_runtime.h>
#include <cuda_fp16.h>
#include <cstdint>

#define NN 50000
#define EE 800000

// ---------------- scratch (device globals — allocation-free) ----------------
__device__ float    g_q[NN * 128];
__device__ float    g_logits[EE * 8];
__device__ float    g_den[NN * 8];
__device__ float    g_aggr[NN * 128];
__device__ int      g_src[EE];
__device__ int      g_dst[EE];
__device__ int      g_is64;
// fp16, SW64-swizzled weight tiles, 8KB each ([n 0..127][k32], 64B rows):
// hk: 0..13 (W1 x10, W2 x4) | hv: 14..27 | hq: 28..35
__device__ char     g_wt[36 * 8192];
// fp16 inputs, row-major
__device__ __align__(16) __half g_ef[(size_t)EE * 64];
__device__ __align__(16) __half g_h[(size_t)NN * 128];
// per-node precomputed W1 partials: P[n][0:128] = h[n]@W1[64:192], [128:256] = h[n]@W1[192:320]
__device__ float    g_pk[(size_t)NN * 256];
__device__ float    g_pv[(size_t)NN * 256];

// ======================= PTX helpers (base-target safe) =======================
__device__ __forceinline__ uint32_t smem_u32(const void* p) {
    uint32_t a;
    asm("{ .reg .u64 t; cvta.to.shared.u64 t, %1; cvt.u32.u64 %0, t; }" : "=r"(a) : "l"(p));
    return a;
}
__device__ __forceinline__ void cpa16(uint32_t dst, const void* src) {
    asm volatile("cp.async.cg.shared.global [%0], [%1], 16;" :: "r"(dst), "l"(src) : "memory");
}
#define CPA_COMMIT() asm volatile("cp.async.commit_group;" ::: "memory")
#define CPA_WAIT(n)  asm volatile("cp.async.wait_group %0;" :: "n"(n) : "memory")

__device__ __forceinline__ void ldsm4(uint32_t* r, uint32_t addr) {
    asm volatile("ldmatrix.sync.aligned.m8n8.x4.shared.b16 {%0,%1,%2,%3}, [%4];"
                 : "=r"(r[0]), "=r"(r[1]), "=r"(r[2]), "=r"(r[3]) : "r"(addr));
}
__device__ __forceinline__ void mma_f16(float* c, const uint32_t* a, uint32_t b0, uint32_t b1) {
    asm volatile("mma.sync.aligned.m16n8k16.row.col.f32.f16.f16.f32 "
                 "{%0,%1,%2,%3}, {%4,%5,%6,%7}, {%8,%9}, {%0,%1,%2,%3};"
                 : "+f"(c[0]), "+f"(c[1]), "+f"(c[2]), "+f"(c[3])
                 : "r"(a[0]), "r"(a[1]), "r"(a[2]), "r"(a[3]), "r"(b0), "r"(b1));
}

#define SW64(o) ((o) ^ (((o) >> 3) & 0x30))

__device__ __forceinline__ unsigned packh2(float a, float b) {
    __half2 t = __floats2half2_rn(a, b);
    return *reinterpret_cast<unsigned*>(&t);
}
__device__ __forceinline__ uint4 packh8(const float* x) {
    return make_uint4(packh2(x[0], x[1]), packh2(x[2], x[3]),
                      packh2(x[4], x[5]), packh2(x[6], x[7]));
}

// =================== setup kernels ===================
__global__ void detect_idx_kernel(const unsigned* __restrict__ raw) {
    if (threadIdx.x == 0 && blockIdx.x == 0) {
        int all_zero = 1;
        for (int i = 1; i < 128; i += 2)
            if (raw[i] != 0u) { all_zero = 0; break; }
        g_is64 = all_zero;
    }
}
__global__ void convert_idx_kernel(const void* __restrict__ raw) {
    int e = blockIdx.x * blockDim.x + threadIdx.x;
    if (e >= EE) return;
    if (g_is64) {
        const long long* p = (const long long*)raw;
        g_src[e] = (int)p[e];  g_dst[e] = (int)p[EE + e];
    } else {
        const int* p = (const int*)raw;
        g_src[e] = p[e];  g_dst[e] = p[EE + e];
    }
}
__global__ void init_kernel() {
    int i = blockIdx.x * blockDim.x + threadIdx.x;
    if (i < NN * 8) g_den[i] = 0.f;
    if (i < NN * 128) g_aggr[i] = 0.f;
}

// convert ef + h to fp16 (once)
__global__ void prep_in(const float* __restrict__ ef, const float* __restrict__ hh) {
    const int totEf = EE * 64 / 8;
    const int totH  = NN * 128 / 8;
    int i = blockIdx.x * blockDim.x + threadIdx.x;
    if (i < totEf) {
        float x[8];
        float4 v0 = *(const float4*)(ef + (size_t)i * 8);
        float4 v1 = *(const float4*)(ef + (size_t)i * 8 + 4);
        x[0]=v0.x; x[1]=v0.y; x[2]=v0.z; x[3]=v0.w; x[4]=v1.x; x[5]=v1.y; x[6]=v1.z; x[7]=v1.w;
        *(uint4*)(g_ef + (size_t)i * 8) = packh8(x);
    } else if (i < totEf + totH) {
        int j = i - totEf;
        float x[8];
        float4 v0 = *(const float4*)(hh + (size_t)j * 8);
        float4 v1 = *(const float4*)(hh + (size_t)j * 8 + 4);
        x[0]=v0.x; x[1]=v0.y; x[2]=v0.z; x[3]=v0.w; x[4]=v1.x; x[5]=v1.y; x[6]=v1.z; x[7]=v1.w;
        *(uint4*)(g_h + (size_t)j * 8) = packh8(x);
    }
}

// fp16 + pre-swizzle hk/hv/hq weights into 32-k SW64 tiles (transposed [n][k])
__global__ void prep_w(const float* __restrict__ k1, const float* __restrict__ k2,
                       const float* __restrict__ v1, const float* __restrict__ v2,
                       const float* __restrict__ q1, const float* __restrict__ q2) {
    int idx = blockIdx.x * blockDim.x + threadIdx.x;
    if (idx >= 36 * 512) return;
    int T = idx >> 9;
    int r2 = idx & 511;
    int n = r2 >> 2, kg = r2 & 3;
    const float* W; int k0;
    if (T < 14)      { int t = T;      W = t < 10 ? k1 : k2; k0 = t < 10 ? t * 32 : (t - 10) * 32; }
    else if (T < 28) { int t = T - 14; W = t < 10 ? v1 : v2; k0 = t < 10 ? t * 32 : (t - 10) * 32; }
    else             { int t = T - 28; W = t < 4  ? q1 : q2; k0 = t < 4  ? t * 32 : (t - 4) * 32; }
    float x[8];
#pragma unroll
    for (int j = 0; j < 8; j++)
        x[j] = W[(size_t)(k0 + kg * 8 + j) * 128 + n];
    *(uint4*)(g_wt + (size_t)T * 8192 + SW64(n * 64 + kg * 16)) = packh8(x);
}

// ---------------- shared mma building block ----------------
#define OFF_W2  49152
#define OFF_PS  81920
#define OFF_PQ  82944
#define OFF_DS  83968
#define OFF_SS  84480
#define MLP_SMEM 84992

__device__ __forceinline__ void mma_chunk32(uint32_t aB, uint32_t bB,
                                            int wrRow, int wcCol, int lid,
                                            float acc[2][8][4]) {
    const int mi  = lid >> 3;
    const int rin = ((mi & 1) << 3) + (lid & 7);
    const int kh  = (mi >> 1) << 4;
    const int nin = ((mi >> 1) << 3) + (lid & 7);
    const int khb = (mi & 1) << 4;
#pragma unroll
    for (int s = 0; s < 2; s++) {
        uint32_t ah[2][4];
#pragma unroll
        for (int mt = 0; mt < 2; mt++)
            ldsm4(ah[mt], aB + SW64((wrRow + mt * 16 + rin) * 64 + s * 32 + kh));
#pragma unroll
        for (int p = 0; p < 4; p++) {
            uint32_t bh4[4];
            ldsm4(bh4, bB + SW64((wcCol + p * 16 + nin) * 64 + s * 32 + khb));
#pragma unroll
            for (int mt = 0; mt < 2; mt++)
#pragma unroll
                for (int ntl = 0; ntl < 2; ntl++)
                    mma_f16(acc[mt][p * 2 + ntl], ah[mt], bh4[ntl * 2], bh4[ntl * 2 + 1]);
        }
    }
}

// ============================================================================
// Node-partial precompute: P[n][colOff:colOff+128] = h[n] @ W1[tiles tb..tb+3]
// NOTE: final iteration must CPA_WAIT(0) — no younger group exists to shield
// chunk 3's group under CPA_WAIT(1). (This was the R12/R15 replay race.)
// ============================================================================
__global__ void __launch_bounds__(256, 2)
gemm_pre(int tb, int colOff, float* __restrict__ outp)
{
    extern __shared__ char smc[];
    const int tid = threadIdx.x;
    const int lid = tid & 31, wid = tid >> 5;
    const int wr = wid >> 1, wc = wid & 1;
    const int row0 = blockIdx.x * 128;
    uint32_t sbase = smem_u32(smc);
    const int arow = tid >> 1, sel = tid & 1;

    auto issueA = [&](int c) {
        int rr = row0 + arow; if (rr >= NN) rr = NN - 1;
        const char* src = (const char*)g_h + (size_t)rr * 256 + c * 64;
        uint32_t ab = sbase + (c % 3) * 16384;
#pragma unroll
        for (int g = 0; g < 2; g++)
            cpa16(ab + SW64(arow * 64 + sel * 32 + g * 16), src + sel * 32 + g * 16);
    };
    auto issueB = [&](int c) {
        const char* src = g_wt + (size_t)(tb + c) * 8192;
        uint32_t bb = sbase + (c % 3) * 16384 + 8192;
#pragma unroll
        for (int i = 0; i < 2; i++) {
            int ix = (tid + i * 256) * 16;
            cpa16(bb + ix, src + ix);
        }
    };

    float acc[2][8][4];
#pragma unroll
    for (int a = 0; a < 2; a++)
#pragma unroll
        for (int b = 0; b < 8; b++)
#pragma unroll
            for (int c = 0; c < 4; c++) acc[a][b][c] = 0.f;

    issueA(0); issueB(0); CPA_COMMIT();
    issueA(1); issueB(1); CPA_COMMIT();
#pragma unroll 1
    for (int c = 0; c < 4; c++) {
        if (c == 3) { CPA_WAIT(0); }   // last chunk's group must be fully drained
        else        { CPA_WAIT(1); }
        __syncthreads();
        mma_chunk32(sbase + (c % 3) * 16384, sbase + (c % 3) * 16384 + 8192,
                    wr * 32, wc * 64, lid, acc);
        if (c + 2 < 4) { issueA(c + 2); issueB(c + 2); CPA_COMMIT(); }
    }

#pragma unroll
    for (int mt = 0; mt < 2; mt++)
#pragma unroll
        for (int rh = 0; rh < 2; rh++) {
            int r = row0 + wr * 32 + mt * 16 + rh * 8 + (lid >> 2);
            if (r < NN) {
#pragma unroll
                for (int nt = 0; nt < 8; nt++)
                    *(float2*)(outp + (size_t)r * 256 + colOff + wc * 64 + nt * 8 + 2 * (lid & 3)) =
                        make_float2(acc[mt][nt][rh * 2], acc[mt][nt][rh * 2 + 1]);
            }
        }
}

// ============================================================================
// fp16 mma MLP. EPI 1/2 (edges): GEMM1 = 2 ef chunks + P[dst]+P[src] fp32 add.
// EPI 0 (q nodes): full NCH-chunk GEMM1. (Tail-safe: W2 group committed at
// NCH-2 shields the final chunk's group under CPA_WAIT(1).)
// ============================================================================
template <int NCH, int MIDX, int W2B, int EPI>
__global__ void __launch_bounds__(256, 2)
mlp_mma(const float* __restrict__ ew, const float* __restrict__ gp,
        const float* __restrict__ B1, const float* __restrict__ G,
        const float* __restrict__ BE, const float* __restrict__ B2)
{
    extern __shared__ char smc[];
    const int tid = threadIdx.x;
    const int lid = tid & 31, wid = tid >> 5;
    const int wr = wid >> 1, wc = wid & 1;
    const int row0 = blockIdx.x * 128;
    uint32_t sbase = smem_u32(smc);
    int*   ds = (int*)(smc + OFF_DS);
    int*   ss = (int*)(smc + OFF_SS);
    float* pS = (float*)(smc + OFF_PS);
    float* pQ = (float*)(smc + OFF_PQ);

    if constexpr (EPI == 1 || EPI == 2) {
        if (tid < 128) { ds[tid] = g_dst[row0 + tid]; ss[tid] = g_src[row0 + tid]; }
    }

    const int arow = tid >> 1, sel = tid & 1;

    auto issueA = [&](int c) {
        const char* src;
        if constexpr (EPI == 0) {
            int rr = row0 + arow; if (rr >= NN) rr = NN - 1;
            src = (const char*)g_h + (size_t)rr * 256 + c * 64;
        } else {
            src = (const char*)g_ef + (size_t)(row0 + arow) * 128 + c * 64;
        }
        uint32_t ab = sbase + (c % 3) * 16384;
#pragma unroll
        for (int g = 0; g < 2; g++)
            cpa16(ab + SW64(arow * 64 + sel * 32 + g * 16), src + sel * 32 + g * 16);
    };
    auto issueB = [&](int c) {
        const char* src = g_wt + (size_t)(MIDX + c) * 8192;
        uint32_t bb = sbase + (c % 3) * 16384 + 8192;
#pragma unroll
        for (int i = 0; i < 2; i++) {
            int ix = (tid + i * 256) * 16;
            cpa16(bb + ix, src + ix);
        }
    };
    auto issueW2 = [&]() {
#pragma unroll
        for (int t = 0; t < 4; t++) {
            const char* src = g_wt + (size_t)(W2B + t) * 8192;
            uint32_t db = sbase + OFF_W2 + t * 8192;
#pragma unroll
            for (int i = 0; i < 2; i++) {
                int ix = (tid + i * 256) * 16;
                cpa16(db + ix, src + ix);
            }
        }
    };

    float acc[2][8][4];
#pragma unroll
    for (int a = 0; a < 2; a++)
#pragma unroll
        for (int b = 0; b < 8; b++)
#pragma unroll
            for (int c = 0; c < 4; c++) acc[a][b][c] = 0.f;

    issueA(0); issueB(0); CPA_COMMIT();
    if (NCH > 1) { issueA(1); issueB(1); CPA_COMMIT(); }

    // ---------------- GEMM1: NCH chunks, 3-stage, 1 sync/iter ----------------
#pragma unroll 1
    for (int c = 0; c < NCH; c++) {
        CPA_WAIT(1);
        __syncthreads();
        mma_chunk32(sbase + (c % 3) * 16384, sbase + (c % 3) * 16384 + 8192,
                    wr * 32, wc * 64, lid, acc);
        if (c + 2 < NCH)       { issueA(c + 2); issueB(c + 2); CPA_COMMIT(); }
        else if (c == NCH - 2) { issueW2(); CPA_COMMIT(); }
    }

    // ---------------- P[dst] + P[src] fp32 gather-add (edges only) ----------------
    if constexpr (EPI == 1 || EPI == 2) {
#pragma unroll
        for (int mt = 0; mt < 2; mt++)
#pragma unroll
            for (int rh = 0; rh < 2; rh++) {
                int rl = wr * 32 + mt * 16 + rh * 8 + (lid >> 2);
                const float* pd = gp + (size_t)ds[rl] * 256 + wc * 64 + 2 * (lid & 3);
                const float* ps = gp + (size_t)ss[rl] * 256 + 128 + wc * 64 + 2 * (lid & 3);
#pragma unroll
                for (int nt = 0; nt < 8; nt++) {
                    float2 a = *(const float2*)(pd + nt * 8);
                    float2 b = *(const float2*)(ps + nt * 8);
                    acc[mt][nt][rh * 2]     += a.x + b.x;
                    acc[mt][nt][rh * 2 + 1] += a.y + b.y;
                }
            }
    }

    // ---------------- bias + LayerNorm (one pass) + ReLU ----------------
    float b1v[16], gv[16], bev[16];
#pragma unroll
    for (int nt = 0; nt < 8; nt++) {
        int col = wc * 64 + nt * 8 + 2 * (lid & 3);
        float2 t0 = *(const float2*)(B1 + col);
        float2 t1 = *(const float2*)(G + col);
        float2 t2 = *(const float2*)(BE + col);
        b1v[nt * 2] = t0.x; b1v[nt * 2 + 1] = t0.y;
        gv[nt * 2]  = t1.x; gv[nt * 2 + 1]  = t1.y;
        bev[nt * 2] = t2.x; bev[nt * 2 + 1] = t2.y;
    }
#pragma unroll
    for (int mt = 0; mt < 2; mt++)
#pragma unroll
        for (int rh = 0; rh < 2; rh++) {
            float sv = 0.f, qv = 0.f;
#pragma unroll
            for (int nt = 0; nt < 8; nt++) {
                float x0 = acc[mt][nt][rh * 2]     + b1v[nt * 2];
                float x1 = acc[mt][nt][rh * 2 + 1] + b1v[nt * 2 + 1];
                acc[mt][nt][rh * 2] = x0; acc[mt][nt][rh * 2 + 1] = x1;
                sv += x0 + x1;
                qv += x0 * x0 + x1 * x1;
            }
            sv += __shfl_xor_sync(0xffffffffu, sv, 1);
            sv += __shfl_xor_sync(0xffffffffu, sv, 2);
            qv += __shfl_xor_sync(0xffffffffu, qv, 1);
            qv += __shfl_xor_sync(0xffffffffu, qv, 2);
            if ((lid & 3) == 0) {
                int rl = wr * 32 + mt * 16 + rh * 8 + (lid >> 2);
                pS[rl * 2 + wc] = sv;
                pQ[rl * 2 + wc] = qv;
            }
        }
    __syncthreads();

    // normalize + relu + pack fp16 -> H tiles in smem (overwrite GEMM1 buffers)
#pragma unroll
    for (int mt = 0; mt < 2; mt++)
#pragma unroll
        for (int rh = 0; rh < 2; rh++) {
            int rl = wr * 32 + mt * 16 + rh * 8 + (lid >> 2);
            float mu = (pS[rl * 2] + pS[rl * 2 + 1]) * 0.0078125f;
            float var = (pQ[rl * 2] + pQ[rl * 2 + 1]) * 0.0078125f - mu * mu;
            float rs = rsqrtf(var + 1e-5f);
#pragma unroll
            for (int nt = 0; nt < 8; nt++) {
                float v0 = fmaxf((acc[mt][nt][rh * 2]     - mu) * rs * gv[nt * 2]     + bev[nt * 2], 0.f);
                float v1 = fmaxf((acc[mt][nt][rh * 2 + 1] - mu) * rs * gv[nt * 2 + 1] + bev[nt * 2 + 1], 0.f);
                int col = wc * 64 + nt * 8 + 2 * (lid & 3);
                uint32_t off = (uint32_t)(col >> 5) * 8192 + SW64(rl * 64 + (col & 31) * 2);
                *(uint32_t*)(smc + off) = packh2(v0, v1);
            }
        }

    CPA_WAIT(0);
    __syncthreads();   // H + W2 resident

    // ---------------- GEMM2: 4 chunks ----------------
    float acc2[2][8][4];
#pragma unroll
    for (int a = 0; a < 2; a++)
#pragma unroll
        for (int b = 0; b < 8; b++)
#pragma unroll
            for (int c = 0; c < 4; c++) acc2[a][b][c] = 0.f;
#pragma unroll
    for (int ch = 0; ch < 4; ch++)
        mma_chunk32(sbase + ch * 8192, sbase + OFF_W2 + ch * 8192,
                    wr * 32, wc * 64, lid, acc2);

    // bias2
#pragma unroll
    for (int nt = 0; nt < 8; nt++) {
        float2 t = *(const float2*)(B2 + wc * 64 + nt * 8 + 2 * (lid & 3));
#pragma unroll
        for (int mt = 0; mt < 2; mt++) {
            acc2[mt][nt][0] += t.x; acc2[mt][nt][1] += t.y;
            acc2[mt][nt][2] += t.x; acc2[mt][nt][3] += t.y;
        }
    }

    // ---------------- epilogues ----------------
#pragma unroll
    for (int mt = 0; mt < 2; mt++)
#pragma unroll
        for (int rh = 0; rh < 2; rh++) {
            int rl = wr * 32 + mt * 16 + rh * 8 + (lid >> 2);
            int r  = row0 + rl;
            if constexpr (EPI == 0) {
                if (r < NN) {
#pragma unroll
                    for (int nt = 0; nt < 8; nt++)
                        *(float2*)(g_q + (size_t)r * 128 + wc * 64 + nt * 8 + 2 * (lid & 3)) =
                            make_float2(acc2[mt][nt][rh * 2], acc2[mt][nt][rh * 2 + 1]);
                }
            } else if constexpr (EPI == 1) {
                int d = ds[rl];
#pragma unroll
                for (int hl = 0; hl < 4; hl++) {
                    float part = 0.f;
#pragma unroll
                    for (int jj = 0; jj < 2; jj++) {
                        int nt = hl * 2 + jj;
                        float2 q2 = *(const float2*)(g_q + (size_t)d * 128 + wc * 64 + nt * 8 + 2 * (lid & 3));
                        part += acc2[mt][nt][rh * 2] * q2.x + acc2[mt][nt][rh * 2 + 1] * q2.y;
                    }
                    part += __shfl_xor_sync(0xffffffffu, part, 1);
                    part += __shfl_xor_sync(0xffffffffu, part, 2);
                    if ((lid & 3) == 0) {
                        int hd = wc * 4 + hl;
                        float lg = part * 0.25f;
                        g_logits[(size_t)r * 8 + hd] = lg;
                        atomicAdd(&g_den[d * 8 + hd], __expf(lg));
                    }
                }
            } else {  // EPI == 2
                int d = ds[rl];
                float eww = ew[r];
#pragma unroll
                for (int hl = 0; hl < 4; hl++) {
                    int hd = wc * 4 + hl;
                    float sc = __expf(g_logits[(size_t)r * 8 + hd]) / g_den[d * 8 + hd] * eww;
#pragma unroll
                    for (int jj = 0; jj < 2; jj++) {
                        int nt = hl * 2 + jj;
                        float* op = g_aggr + (size_t)d * 128 + wc * 64 + nt * 8 + 2 * (lid & 3);
                        asm volatile("red.global.add.v2.f32 [%0], {%1,%2};" ::
                            "l"(op), "f"(acc2[mt][nt][rh * 2] * sc),
                                     "f"(acc2[mt][nt][rh * 2 + 1] * sc) : "memory");
                    }
                }
            }
        }
}

// ============================================================================
// SIMT fp32 fused MLP for the output MLP (exact, wide error margin)
// ============================================================================
#define HSTR 132

__global__ void __launch_bounds__(256, 2)
fused_out(const float* __restrict__ hh,
          const float* __restrict__ W1, const float* __restrict__ B1,
          const float* __restrict__ G,  const float* __restrict__ BE,
          const float* __restrict__ W2, const float* __restrict__ B2,
          float* __restrict__ outp)
{
    extern __shared__ float sm[];
    float* As = sm;
    float* Bs = sm + 16 * 128;
    float* Hs = sm + 32 * 128;

    const int tid   = threadIdx.x;
    const int tx    = tid & 15;
    const int ty    = tid >> 4;
    const int row0  = blockIdx.x * 128;
    const int myrow = ty * 8;
    const int mycol = tx * 8;
    const int rowL  = tid & 127;
    const int kL    = (tid >> 7) * 8;

    int rL = row0 + rowL;
    if (rL >= NN) rL = NN - 1;

    auto a_ptr = [&](int k0) -> const float* {
        int kk = k0 + kL;
        return (kk < 128) ? (g_aggr + (size_t)rL * 128 + kk)
                          : (hh + (size_t)rL * 128 + (kk - 128));
    };

    float acc[8][8];
#pragma unroll
    for (int i = 0; i < 8; i++)
#pragma unroll
        for (int j = 0; j < 8; j++) acc[i][j] = 0.f;

    float4 pa0 = *(const float4*)(a_ptr(0));
    float4 pa1 = *(const float4*)(a_ptr(0) + 4);
    const float* wsrc = W1 + (size_t)ty * 128 + mycol;
    float4 pb0 = *(const float4*)(wsrc);
    float4 pb1 = *(const float4*)(wsrc + 4);

#pragma unroll 1
    for (int k0 = 0; k0 < 256; k0 += 16) {
        As[(kL + 0) * 128 + rowL] = pa0.x;
        As[(kL + 1) * 128 + rowL] = pa0.y;
        As[(kL + 2) * 128 + rowL] = pa0.z;
        As[(kL + 3) * 128 + rowL] = pa0.w;
        As[(kL + 4) * 128 + rowL] = pa1.x;
        As[(kL + 5) * 128 + rowL] = pa1.y;
        As[(kL + 6) * 128 + rowL] = pa1.z;
        As[(kL + 7) * 128 + rowL] = pa1.w;
        *(float4*)(Bs + ty * 128 + mycol)     = pb0;
        *(float4*)(Bs + ty * 128 + mycol + 4) = pb1;
        __syncthreads();

        if (k0 + 16 < 256) {
            pa0 = *(const float4*)(a_ptr(k0 + 16));
            pa1 = *(const float4*)(a_ptr(k0 + 16) + 4);
            const float* ws = W1 + (size_t)(k0 + 16 + ty) * 128 + mycol;
            pb0 = *(const float4*)(ws);
            pb1 = *(const float4*)(ws + 4);
        }
#pragma unroll
        for (int k = 0; k < 16; k++) {
            float4 a0 = *(float4*)(As + k * 128 + myrow);
            float4 a1 = *(float4*)(As + k * 128 + myrow + 4);
            float4 b0 = *(float4*)(Bs + k * 128 + mycol);
            float4 b1 = *(float4*)(Bs + k * 128 + mycol + 4);
            float a[8] = {a0.x, a0.y, a0.z, a0.w, a1.x, a1.y, a1.z, a1.w};
            float b[8] = {b0.x, b0.y, b0.z, b0.w, b1.x, b1.y, b1.z, b1.w};
#pragma unroll
            for (int i = 0; i < 8; i++)
#pragma unroll
                for (int j = 0; j < 8; j++)
                    acc[i][j] += a[i] * b[j];
        }
        __syncthreads();
    }

    {
        float gv[8], bev[8], b1v[8];
#pragma unroll
        for (int j = 0; j < 8; j++) {
            gv[j] = G[mycol + j]; bev[j] = BE[mycol + j]; b1v[j] = B1[mycol + j];
        }
#pragma unroll
        for (int i = 0; i < 8; i++) {
            float s = 0.f;
#pragma unroll
            for (int j = 0; j < 8; j++) { acc[i][j] += b1v[j]; s += acc[i][j]; }
            s += __shfl_xor_sync(0xffffffffu, s, 1);
            s += __shfl_xor_sync(0xffffffffu, s, 2);
            s += __shfl_xor_sync(0xffffffffu, s, 4);
            s += __shfl_xor_sync(0xffffffffu, s, 8);
            float mu = s * 0.0078125f;
            float s2 = 0.f;
#pragma unroll
            for (int j = 0; j < 8; j++) { float d = acc[i][j] - mu; s2 += d * d; }
            s2 += __shfl_xor_sync(0xffffffffu, s2, 1);
            s2 += __shfl_xor_sync(0xffffffffu, s2, 2);
            s2 += __shfl_xor_sync(0xffffffffu, s2, 4);
            s2 += __shfl_xor_sync(0xffffffffu, s2, 8);
            float rs = rsqrtf(s2 * 0.0078125f + 1e-5f);
#pragma unroll
            for (int j = 0; j < 8; j++)
                Hs[(myrow + i) * HSTR + mycol + j] =
                    fmaxf((acc[i][j] - mu) * rs * gv[j] + bev[j], 0.f);
        }
    }
    __syncthreads();

    float ac2[8][8];
#pragma unroll
    for (int i = 0; i < 8; i++)
#pragma unroll
        for (int j = 0; j < 8; j++) ac2[i][j] = 0.f;

    {
        const float* ws = W2 + (size_t)ty * 128 + mycol;
        pb0 = *(const float4*)(ws);
        pb1 = *(const float4*)(ws + 4);
    }
#pragma unroll 1
    for (int k0 = 0; k0 < 128; k0 += 16) {
        *(float4*)(Bs + ty * 128 + mycol)     = pb0;
        *(float4*)(Bs + ty * 128 + mycol + 4) = pb1;
        __syncthreads();
        if (k0 + 16 < 128) {
            const float* ws = W2 + (size_t)(k0 + 16 + ty) * 128 + mycol;
            pb0 = *(const float4*)(ws);
            pb1 = *(const float4*)(ws + 4);
        }
#pragma unroll
        for (int kb = 0; kb < 16; kb += 2) {
            float2 av[8];
#pragma unroll
            for (int i = 0; i < 8; i++)
                av[i] = *(float2*)(Hs + (myrow + i) * HSTR + k0 + kb);
#pragma unroll
            for (int kk = 0; kk < 2; kk++) {
                int k = kb + kk;
                float4 b0 = *(float4*)(Bs + k * 128 + mycol);
                float4 b1 = *(float4*)(Bs + k * 128 + mycol + 4);
                float b[8] = {b0.x, b0.y, b0.z, b0.w, b1.x, b1.y, b1.z, b1.w};
#pragma unroll
                for (int i = 0; i < 8; i++) {
                    float a = kk ? av[i].y : av[i].x;
#pragma unroll
                    for (int j = 0; j < 8; j++)
                        ac2[i][j] += a * b[j];
                }
            }
        }
        __syncthreads();
    }
#pragma unroll
    for (int j = 0; j < 8; j++) {
        float b2v = B2[mycol + j];
#pragma unroll
        for (int i = 0; i < 8; i++) ac2[i][j] += b2v;
    }

#pragma unroll
    for (int i = 0; i < 8; i++) {
        int r = row0 + myrow + i;
        if (r < NN) {
            *(float4*)(outp + (size_t)r * 128 + mycol) =
                make_float4(ac2[i][0], ac2[i][1], ac2[i][2], ac2[i][3]);
            *(float4*)(outp + (size_t)r * 128 + mycol + 4) =
                make_float4(ac2[i][4], ac2[i][5], ac2[i][6], ac2[i][7]);
        }
    }
}

static const int NODE_SMEM = (32 * 128 + 128 * HSTR) * 4;

extern "C" void kernel_launch(void* const* d_in, const int* in_sizes, int n_in,
                              void* d_out, int out_size)
{
    const float* hPtr = (const float*)d_in[0];
    const float* ef   = (const float*)d_in[1];
    const float* ew   = (const float*)d_in[2];
    const void*  eidx = (const void*)d_in[3];
    const float* hk[6], *hv[6], *hq[6], *no[6];
    for (int i = 0; i < 6; i++) {
        hk[i] = (const float*)d_in[4 + i];
        hv[i] = (const float*)d_in[10 + i];
        hq[i] = (const float*)d_in[16 + i];
        no[i] = (const float*)d_in[22 + i];
    }
    float* outp = (float*)d_out;

    float* pkPtr; cudaGetSymbolAddress((void**)&pkPtr, g_pk);
    float* pvPtr; cudaGetSymbolAddress((void**)&pvPtr, g_pv);

    cudaFuncSetAttribute(gemm_pre, cudaFuncAttributeMaxDynamicSharedMemorySize, MLP_SMEM);
    cudaFuncSetAttribute(mlp_mma<4, 28, 32, 0>, cudaFuncAttributeMaxDynamicSharedMemorySize, MLP_SMEM);
    cudaFuncSetAttribute(mlp_mma<2, 0, 10, 1>, cudaFuncAttributeMaxDynamicSharedMemorySize, MLP_SMEM);
    cudaFuncSetAttribute(mlp_mma<2, 14, 24, 2>, cudaFuncAttributeMaxDynamicSharedMemorySize, MLP_SMEM);
    cudaFuncSetAttribute(fused_out, cudaFuncAttributeMaxDynamicSharedMemorySize, NODE_SMEM);

    const int nodeBlocks = (NN + 127) / 128;           // 391
    const int edgeBlocks = EE / 128;                   // 6250
    const int flatBlocks = (NN * 128 + 255) / 256;
    const int idxBlocks  = (EE + 255) / 256;
    const int prepBlocks = (EE * 64 / 8 + NN * 128 / 8 + 255) / 256;

    detect_idx_kernel<<<1, 32>>>((const unsigned*)eidx);
    convert_idx_kernel<<<idxBlocks, 256>>>(eidx);
    prep_w<<<72, 256>>>(hk[0], hk[4], hv[0], hv[4], hq[0], hq[4]);
    prep_in<<<prepBlocks, 256>>>(ef, hPtr);
    init_kernel<<<flatBlocks, 256>>>();

    // per-node W1 partials: P_k, P_v (dst half = tiles +2..+5, src half = +6..+9)
    gemm_pre<<<nodeBlocks, 256, MLP_SMEM>>>(2, 0, pkPtr);
    gemm_pre<<<nodeBlocks, 256, MLP_SMEM>>>(6, 128, pkPtr);
    gemm_pre<<<nodeBlocks, 256, MLP_SMEM>>>(16, 0, pvPtr);
    gemm_pre<<<nodeBlocks, 256, MLP_SMEM>>>(20, 128, pvPtr);

    // q = MLP_hq(h)  (fp16 mma)
    mlp_mma<4, 28, 32, 0><<<nodeBlocks, 256, MLP_SMEM>>>(
        nullptr, nullptr, hq[1], hq[2], hq[3], hq[5]);

    // k-MLP + logits + den (ef GEMM + P_k gather)
    mlp_mma<2, 0, 10, 1><<<edgeBlocks, 256, MLP_SMEM>>>(
        nullptr, pkPtr, hk[1], hk[2], hk[3], hk[5]);

    // v-MLP + alpha*e_w*v scatter (ef GEMM + P_v gather)
    mlp_mma<2, 14, 24, 2><<<edgeBlocks, 256, MLP_SMEM>>>(
        ew, pvPtr, hv[1], hv[2], hv[3], hv[5]);

    // out = MLP_no([aggr | h])  (SIMT fp32, exact)
    fused_out<<<nodeBlocks, 256, NODE_SMEM>>>(
        hPtr, no[0], no[1], no[2], no[3], no[4], no[5], outp);
}